// round 15
// baseline (speedup 1.0000x reference)
#include <cuda_runtime.h>
#include <cuda_bf16.h>
#include <cuda_fp16.h>
#include <cstdint>

// ---------------------------------------------------------------------------
// Swin shifted-window attention, B=32 H=W=56 C=512 NH=16 HD=32 WS=7 SS=3
//   k0: build row-index table
//   kw: convert weights fp32 -> fp16
//   kx: convert+gather x     -> g_a_h (fp16, window-row order)
//   k1: QKV GEMM  mma.sync fp16, cp.async 6-stage -> g_qkvh (fp16)
//   k2: attention per (window, head), tensor-core FA2-style -> g_att_h
//   k3: proj GEMM (scatter-C) -> out (fp32)
//
// R14 -> R15: GEMM was ldmatrix/L1-bound (L1=82.5% > tensor=49%). Warp tile
// 32x64 -> 64x64 (128-thr CTA, 4 warps 2x2, 128 acc regs, launch_bounds
// (128,2)): LDSM bytes per MMA 192 -> 128. Cache hints swapped per grid
// order (bn fast => co-resident CTAs share A): A .ca, B .cg.
// tcgen05 unavailable (plain sm_103 ptxas target) -> mma.sync + ldmatrix.
// ---------------------------------------------------------------------------

#define BATCH   32
#define IMG     56
#define CCH     512
#define NHEAD   16
#define HD      32
#define WS      7
#define SS      3
#define NTOK    49
#define TOTWIN  2048
#define MROWS   100352
#define QKVC    1536

// scratch (device globals: allocation-free; NEVER passed from host)
__device__ int   g_rowidx[MROWS];
__device__ __half g_qkvh[(size_t)MROWS * QKVC];
__device__ __half g_a_h[(size_t)MROWS * CCH];
__device__ __half g_att_h[(size_t)MROWS * CCH];
__device__ __half g_wqkv_h[QKVC * CCH];
__device__ __half g_wp_h[CCH * CCH];

__device__ __forceinline__ uint32_t smem_u32(const void* p) {
    uint32_t a;
    asm("{ .reg .u64 t; cvta.to.shared.u64 t, %1; cvt.u32.u64 %0, t; }"
        : "=r"(a) : "l"(p));
    return a;
}
__device__ __forceinline__ uint32_t pack2h(__half a, __half b) {
    return ((uint32_t)__half_as_ushort(b) << 16) | __half_as_ushort(a);
}

#define LDSM4(r0, r1, r2, r3, addr)                                            \
    asm volatile("ldmatrix.sync.aligned.m8n8.x4.shared.b16 {%0,%1,%2,%3}, [%4];" \
                 : "=r"(r0), "=r"(r1), "=r"(r2), "=r"(r3) : "r"(addr))
#define LDSM4T(r0, r1, r2, r3, addr)                                           \
    asm volatile("ldmatrix.sync.aligned.m8n8.x4.trans.shared.b16 {%0,%1,%2,%3}, [%4];" \
                 : "=r"(r0), "=r"(r1), "=r"(r2), "=r"(r3) : "r"(addr))

#define MMA_FP16(d, a, b)                                                      \
    asm volatile("mma.sync.aligned.m16n8k16.row.col.f32.f16.f16.f32 "          \
                 "{%0,%1,%2,%3}, {%4,%5,%6,%7}, {%8,%9}, {%0,%1,%2,%3};"       \
                 : "+f"((d)[0]), "+f"((d)[1]), "+f"((d)[2]), "+f"((d)[3])      \
                 : "r"((a)[0]), "r"((a)[1]), "r"((a)[2]), "r"((a)[3]),         \
                   "r"((b)[0]), "r"((b)[1]))

__device__ __forceinline__ void cpa16_cg(uint32_t dst, const void* src) {
    asm volatile("cp.async.cg.shared.global [%0], [%1], 16;"
                 :: "r"(dst), "l"(src) : "memory");
}
__device__ __forceinline__ void cpa16_ca(uint32_t dst, const void* src) {
    asm volatile("cp.async.ca.shared.global [%0], [%1], 16;"
                 :: "r"(dst), "l"(src) : "memory");
}
#define CP_COMMIT() asm volatile("cp.async.commit_group;" ::: "memory")
#define CP_WAIT4()  asm volatile("cp.async.wait_group 4;" ::: "memory")

// ---------------------------------------------------------------------------
__global__ void build_rowidx_kernel() {
    int m = blockIdx.x * 256 + threadIdx.x;
    if (m >= MROWS) return;
    int win = m / NTOK, n = m % NTOK;
    int b  = win >> 6, wi = win & 63;
    int r = (wi >> 3) * WS + n / WS;
    int c = (wi & 7) * WS + n % WS;
    int sh = r + SS; if (sh >= IMG) sh -= IMG;
    int sw = c + SS; if (sw >= IMG) sw -= IMG;
    g_rowidx[m] = (b * IMG + sh) * IMG + sw;
}

__global__ void convert_w_kernel(const float* __restrict__ qkv_w,
                                 const float* __restrict__ proj_w) {
    int i = blockIdx.x * 256 + threadIdx.x;
    if (i < QKVC * CCH) g_wqkv_h[i] = __float2half_rn(qkv_w[i]);
    if (i < CCH * CCH)  g_wp_h[i]   = __float2half_rn(proj_w[i]);
}

// gather x through rowidx, fp16 (window-row order)
__global__ void convert_x_kernel(const float* __restrict__ x) {
    size_t i = (size_t)blockIdx.x * 256 + threadIdx.x;   // over MROWS*128
    if (i >= (size_t)MROWS * 128) return;
    int m = (int)(i >> 7);
    int c4 = (int)(i & 127) << 2;
    float4 v = *(const float4*)(x + (size_t)g_rowidx[m] * CCH + c4);
    uint2 hp;
    hp.x = pack2h(__float2half_rn(v.x), __float2half_rn(v.y));
    hp.y = pack2h(__float2half_rn(v.z), __float2half_rn(v.w));
    *(uint2*)(g_a_h + (size_t)m * CCH + c4) = hp;
}

// ---------------------------------------------------------------------------
// mma.sync fp16 GEMM: BM=BN=128, BK=32, 128 thr (4 warps 2x2, warp tile
// 64x64, 128 acc regs). cp.async 6-stage pipeline (5 in flight), 2 CTA/SM.
// Stage (16KB): A @0, B @8KB; 128 rows x 64B, chunk-swizzled:
//   phys_chunk = c ^ ((r>>1)&3) ^ ((r>>3)&1)
// Grid has bn fast => co-resident CTAs share A tile: A loads .ca, B .cg.
// QKV=true : C -> g_qkvh (fp16).  QKV=false: C -> out fp32, rowidx scatter.
// ---------------------------------------------------------------------------
#define AOFF 0
#define BOFF 8192
#define BUFB 16384
#define NSTG 6
#define NKCH 16            // 512/32
#define SMEM_DYN (NSTG * BUFB)

__device__ __forceinline__ uint32_t swz(int r, int c) {
    return (uint32_t)(r * 64 + ((c ^ ((r >> 1) & 3) ^ ((r >> 3) & 1)) << 4));
}

template <bool QKV>
__global__ __launch_bounds__(128, 2)
void gemm_mma_kernel(const float* __restrict__ bias,
                     float* __restrict__ out)
{
    extern __shared__ char smem[];
    const uint32_t sbase = smem_u32(smem);
    const int tid = threadIdx.x;
    const int lane = tid & 31, warp = tid >> 5;
    const int wm = warp >> 1, wn = warp & 1;       // 2x2 warp grid
    const int bm = blockIdx.y * 128, bn = blockIdx.x * 128;

    const __half* __restrict__ Aw = QKV ? g_a_h : g_att_h;
    const __half* __restrict__ Bw = QKV ? g_wqkv_h : g_wp_h;

    // loader: thread t owns row t of both A and B tiles (64B = 4x16B each)
    const size_t ga = (size_t)(bm + tid) * CCH;
    const size_t gb = (size_t)(bn + tid) * CCH;
    uint32_t sto[4];
#pragma unroll
    for (int c = 0; c < 4; c++) sto[c] = swz(tid, c);

    auto issue = [&](int kt, int s) {
        uint32_t b = sbase + s * BUFB;
        const __half* pa = Aw + ga + kt * 32;
        const __half* pb = Bw + gb + kt * 32;
#pragma unroll
        for (int c = 0; c < 4; c++) {
            cpa16_ca(b + AOFF + sto[c], pa + c * 8);   // A: L1 (shared by pair)
            cpa16_cg(b + BOFF + sto[c], pb + c * 8);   // B: bypass L1
        }
        CP_COMMIT();
    };

    // per-lane ldmatrix offsets (stage-relative)
    const int lane15 = lane & 15;
    uint32_t aoff_[2][4], boff[2][4];
#pragma unroll
    for (int s = 0; s < 2; s++) {
#pragma unroll
        for (int mt = 0; mt < 4; mt++) {
            int r = wm * 64 + mt * 16 + lane15;
            aoff_[s][mt] = swz(r, 2 * s + (lane >> 4));
        }
#pragma unroll
        for (int p = 0; p < 4; p++) {
            int n = wn * 64 + p * 16 + ((lane >> 4) & 1) * 8 + (lane & 7);
            boff[s][p] = swz(n, 2 * s + ((lane >> 3) & 1));
        }
    }

    float acc[4][8][4];
#pragma unroll
    for (int mt = 0; mt < 4; mt++)
#pragma unroll
        for (int nt = 0; nt < 8; nt++)
#pragma unroll
            for (int j = 0; j < 4; j++) acc[mt][nt][j] = 0.f;

    auto compute = [&](uint32_t bb) {
#pragma unroll
        for (int s = 0; s < 2; s++) {
            uint32_t ah[4][4], bh_[8][2];
#pragma unroll
            for (int mt = 0; mt < 4; mt++)
                LDSM4(ah[mt][0], ah[mt][1], ah[mt][2], ah[mt][3],
                      bb + AOFF + aoff_[s][mt]);
#pragma unroll
            for (int p = 0; p < 4; p++) {
                uint32_t t0, t1, t2, t3;
                LDSM4(t0, t1, t2, t3, bb + BOFF + boff[s][p]);
                bh_[2 * p][0] = t0; bh_[2 * p][1] = t1;
                bh_[2 * p + 1][0] = t2; bh_[2 * p + 1][1] = t3;
            }
#pragma unroll
            for (int mt = 0; mt < 4; mt++)
#pragma unroll
                for (int nt = 0; nt < 8; nt++)
                    MMA_FP16(acc[mt][nt], ah[mt], bh_[nt]);
        }
    };

    // ---- pipeline: 5 chunks in flight, 6 stages ----
    issue(0, 0); issue(1, 1); issue(2, 2); issue(3, 3); issue(4, 4);
    for (int kt = 0; kt < NKCH; kt++) {
        CP_WAIT4();                 // 5 groups pending at top -> kt complete
        __syncthreads();            // all warps done with stage being reused
        if (kt + 5 < NKCH) issue(kt + 5, (kt + 5) % NSTG);
        else               CP_COMMIT();     // keep group count uniform
        compute(sbase + (kt % NSTG) * BUFB);
    }

    // ---- epilogue ----
#pragma unroll
    for (int mt = 0; mt < 4; mt++) {
        int mr = bm + wm * 64 + mt * 16 + (lane >> 2);
        const int cbase = bn + wn * 64 + 2 * (lane & 3);
        if (QKV) {
            size_t r0 = (size_t)mr * QKVC, r1 = (size_t)(mr + 8) * QKVC;
#pragma unroll
            for (int nt = 0; nt < 8; nt++) {
                float2 bb = *(const float2*)(bias + cbase + nt * 8);
                uint32_t u0 = pack2h(__float2half_rn(acc[mt][nt][0] + bb.x),
                                     __float2half_rn(acc[mt][nt][1] + bb.y));
                uint32_t u1 = pack2h(__float2half_rn(acc[mt][nt][2] + bb.x),
                                     __float2half_rn(acc[mt][nt][3] + bb.y));
                *(uint32_t*)(g_qkvh + r0 + cbase + nt * 8) = u0;
                *(uint32_t*)(g_qkvh + r1 + cbase + nt * 8) = u1;
            }
        } else {
            size_t r0 = (size_t)g_rowidx[mr] * CCH;
            size_t r1 = (size_t)g_rowidx[mr + 8] * CCH;
            float* p0 = out + r0 + cbase;
            float* p1 = out + r1 + cbase;
#pragma unroll
            for (int nt = 0; nt < 8; nt++) {
                float2 bb = *(const float2*)(bias + cbase + nt * 8);
                float2 v0, v1;
                v0.x = acc[mt][nt][0] + bb.x; v0.y = acc[mt][nt][1] + bb.y;
                v1.x = acc[mt][nt][2] + bb.x; v1.y = acc[mt][nt][3] + bb.y;
                *(float2*)(p0 + nt * 8) = v0;
                *(float2*)(p1 + nt * 8) = v1;
            }
        }
    }
}

// ---------------------------------------------------------------------------
// Attention: block = (window, head), 128 thr = 4 warps, warp = one m16 tile.
// q/k/v fp16 in smem (row stride 40 halves = 80B, conflict-free ldmatrix).
// S via mma fragments, in-register softmax (quad shfl_xor), P repacked to
// A-frags in registers, PV via trans ldmatrix. Bias matrix (rel-pos + shift
// mask, cols 49-55 = -1e30, pad rows 0) built per block. (unchanged)
// ---------------------------------------------------------------------------
#define ASTR 40

__global__ __launch_bounds__(128)
void attn_kernel(const float* __restrict__ rel)
{
    const int win = blockIdx.x >> 4;
    const int h   = blockIdx.x & 15;
    const int tid = threadIdx.x;
    const int lane = tid & 31, warp = tid >> 5;

    __shared__ __align__(16) __half qs[64 * ASTR];
    __shared__ __align__(16) __half ks[64 * ASTR];
    __shared__ __align__(16) __half vs[64 * ASTR];
    __shared__ float bm_s[64 * 56];
    __shared__ float tb[169];
    __shared__ int   lab[NTOK];

    for (int i = tid; i < 169; i += 128)
        tb[i] = rel[i * NHEAD + h];
    if (tid < NTOK) {
        int wi = win & 63;
        int r = (wi >> 3) * WS + tid / WS;
        int c = (wi & 7) * WS + tid % WS;
        int rh = (r < IMG - WS) ? 0 : (r < IMG - SS ? 1 : 2);
        int rw = (c < IMG - WS) ? 0 : (c < IMG - SS ? 1 : 2);
        lab[tid] = rh * 3 + rw;
    }
    const size_t base = (size_t)(win * NTOK) * QKVC + h * HD;
    for (int e = tid; e < NTOK * 8; e += 128) {
        int n = e >> 3, c4 = (e & 7) * 4;
        const __half* p = g_qkvh + base + (size_t)n * QKVC + c4;
        *(uint2*)&qs[n * ASTR + c4] = *(const uint2*)(p);
        *(uint2*)&ks[n * ASTR + c4] = *(const uint2*)(p + 512);
        *(uint2*)&vs[n * ASTR + c4] = *(const uint2*)(p + 1024);
    }
    for (int e = tid; e < 15 * 8; e += 128) {     // zero pad rows 49..63
        int n = NTOK + (e >> 3), c4 = (e & 7) * 4;
        *(uint2*)&qs[n * ASTR + c4] = make_uint2(0, 0);
        *(uint2*)&ks[n * ASTR + c4] = make_uint2(0, 0);
        *(uint2*)&vs[n * ASTR + c4] = make_uint2(0, 0);
    }
    __syncthreads();

    for (int idx = tid; idx < 64 * 56; idx += 128) {
        int r = idx / 56, c = idx % 56;
        float v;
        if (r >= NTOK)      v = 0.0f;
        else if (c >= NTOK) v = -1e30f;
        else {
            int rr = r / WS, rm = r % WS, cr = c / WS, cm = c % WS;
            v = tb[(rr - cr + 6) * 13 + (rm - cm + 6)];
            if (lab[r] != lab[c]) v -= 100.0f;
        }
        bm_s[idx] = v;
    }
    __syncthreads();

    const int m0 = warp * 16;
    const int g = lane >> 2, t = lane & 3;
    const int lane15 = lane & 15, lhalf = lane >> 4;
    const uint32_t qb = smem_u32(qs), kb = smem_u32(ks), vb = smem_u32(vs);

    uint32_t af[2][4];
    {
        uint32_t aa = qb + ((m0 + lane15) * ASTR + lhalf * 8) * 2;
        LDSM4(af[0][0], af[0][1], af[0][2], af[0][3], aa);
        LDSM4(af[1][0], af[1][1], af[1][2], af[1][3], aa + 32);
    }

    float sacc[7][4];
#pragma unroll
    for (int j = 0; j < 7; j++)
#pragma unroll
        for (int i = 0; i < 4; i++) sacc[j][i] = 0.f;

#pragma unroll
    for (int nc = 0; nc < 4; nc++) {
        uint32_t ka = kb + ((nc * 16 + lane15) * ASTR + lhalf * 8) * 2;
#pragma unroll
        for (int kk = 0; kk < 2; kk++) {
            uint32_t r0, r1, r2, r3;
            LDSM4(r0, r1, r2, r3, ka + kk * 32);
            uint32_t blo[2] = { r0, r2 };
            uint32_t bhi[2] = { r1, r3 };
            MMA_FP16(sacc[2 * nc], af[kk], blo);
            if (2 * nc + 1 < 7) MMA_FP16(sacc[2 * nc + 1], af[kk], bhi);
        }
    }

    const float scale = 0.17677669529663687f;   // 32^-0.5
    const int r_lo = m0 + g, r_hi = m0 + g + 8;
#pragma unroll
    for (int j = 0; j < 7; j++) {
        int c0 = j * 8 + 2 * t;
        sacc[j][0] = sacc[j][0] * scale + bm_s[r_lo * 56 + c0];
        sacc[j][1] = sacc[j][1] * scale + bm_s[r_lo * 56 + c0 + 1];
        sacc[j][2] = sacc[j][2] * scale + bm_s[r_hi * 56 + c0];
        sacc[j][3] = sacc[j][3] * scale + bm_s[r_hi * 56 + c0 + 1];
    }
    float mlo = -1e30f, mhi = -1e30f;
#pragma unroll
    for (int j = 0; j < 7; j++) {
        mlo = fmaxf(mlo, fmaxf(sacc[j][0], sacc[j][1]));
        mhi = fmaxf(mhi, fmaxf(sacc[j][2], sacc[j][3]));
    }
    mlo = fmaxf(mlo, __shfl_xor_sync(0xffffffffu, mlo, 1));
    mlo = fmaxf(mlo, __shfl_xor_sync(0xffffffffu, mlo, 2));
    mhi = fmaxf(mhi, __shfl_xor_sync(0xffffffffu, mhi, 1));
    mhi = fmaxf(mhi, __shfl_xor_sync(0xffffffffu, mhi, 2));
    float slo = 0.f, shi = 0.f;
#pragma unroll
    for (int j = 0; j < 7; j++) {
        sacc[j][0] = __expf(sacc[j][0] - mlo);
        sacc[j][1] = __expf(sacc[j][1] - mlo);
        sacc[j][2] = __expf(sacc[j][2] - mhi);
        sacc[j][3] = __expf(sacc[j][3] - mhi);
        slo += sacc[j][0] + sacc[j][1];
        shi += sacc[j][2] + sacc[j][3];
    }
    slo += __shfl_xor_sync(0xffffffffu, slo, 1);
    slo += __shfl_xor_sync(0xffffffffu, slo, 2);
    shi += __shfl_xor_sync(0xffffffffu, shi, 1);
    shi += __shfl_xor_sync(0xffffffffu, shi, 2);
    const float ilo = 1.0f / slo, ihi = 1.0f / shi;

    uint32_t pf[7][2];
#pragma unroll
    for (int j = 0; j < 7; j++) {
        pf[j][0] = pack2h(__float2half_rn(sacc[j][0] * ilo),
                          __float2half_rn(sacc[j][1] * ilo));
        pf[j][1] = pack2h(__float2half_rn(sacc[j][2] * ihi),
                          __float2half_rn(sacc[j][3] * ihi));
    }

    float oacc[4][4];
#pragma unroll
    for (int nt = 0; nt < 4; nt++)
#pragma unroll
        for (int i = 0; i < 4; i++) oacc[nt][i] = 0.f;

    const int grp = lane >> 3, lr8 = lane & 7;
    const int vrow_off = lr8 + ((grp & 1) ? 8 : 0);
    const int vcol_off = (grp >= 2) ? 8 : 0;
#pragma unroll
    for (int kk = 0; kk < 4; kk++) {
        uint32_t a[4];
        a[0] = pf[2 * kk][0];
        a[1] = pf[2 * kk][1];
        a[2] = (2 * kk + 1 < 7) ? pf[2 * kk + 1][0] : 0u;
        a[3] = (2 * kk + 1 < 7) ? pf[2 * kk + 1][1] : 0u;
#pragma unroll
        for (int nv = 0; nv < 2; nv++) {
            uint32_t va = vb + ((kk * 16 + vrow_off) * ASTR + nv * 16 + vcol_off) * 2;
            uint32_t r0, r1, r2, r3;
            LDSM4T(r0, r1, r2, r3, va);
            uint32_t b0[2] = { r0, r1 };
            uint32_t b1[2] = { r2, r3 };
            MMA_FP16(oacc[2 * nv], a, b0);
            MMA_FP16(oacc[2 * nv + 1], a, b1);
        }
    }

    const size_t obase = (size_t)(win * NTOK) * CCH + h * HD;
    if (r_lo < NTOK) {
        size_t rb = obase + (size_t)r_lo * CCH;
#pragma unroll
        for (int nt = 0; nt < 4; nt++) {
            int col = nt * 8 + 2 * t;
            *(uint32_t*)(g_att_h + rb + col) =
                pack2h(__float2half_rn(oacc[nt][0]), __float2half_rn(oacc[nt][1]));
        }
    }
    if (r_hi < NTOK) {
        size_t rb = obase + (size_t)r_hi * CCH;
#pragma unroll
        for (int nt = 0; nt < 4; nt++) {
            int col = nt * 8 + 2 * t;
            *(uint32_t*)(g_att_h + rb + col) =
                pack2h(__float2half_rn(oacc[nt][2]), __float2half_rn(oacc[nt][3]));
        }
    }
}

// ---------------------------------------------------------------------------
extern "C" void kernel_launch(void* const* d_in, const int* in_sizes, int n_in,
                              void* d_out, int out_size)
{
    const float* x      = (const float*)d_in[0];
    const float* qkv_w  = (const float*)d_in[1];
    const float* qkv_b  = (const float*)d_in[2];
    const float* proj_w = (const float*)d_in[3];
    const float* proj_b = (const float*)d_in[4];
    const float* rel    = (const float*)d_in[5];
    float* out = (float*)d_out;

    cudaFuncSetAttribute(gemm_mma_kernel<true>,
                         cudaFuncAttributeMaxDynamicSharedMemorySize, SMEM_DYN);
    cudaFuncSetAttribute(gemm_mma_kernel<false>,
                         cudaFuncAttributeMaxDynamicSharedMemorySize, SMEM_DYN);

    build_rowidx_kernel<<<(MROWS + 255) / 256, 256>>>();
    convert_w_kernel<<<(QKVC * CCH + 255) / 256, 256>>>(qkv_w, proj_w);
    convert_x_kernel<<<(int)(((size_t)MROWS * 128 + 255) / 256), 256>>>(x);

    // QKV: M=100352, N=1536 -> fp16 g_qkvh
    gemm_mma_kernel<true><<<dim3(QKVC / 128, MROWS / 128), 128, SMEM_DYN>>>(
        qkv_b, nullptr);

    attn_kernel<<<TOTWIN * NHEAD, 128>>>(rel);

    // proj: M=100352, N=512 (A = g_att_h, scatter-C to out)
    gemm_mma_kernel<false><<<dim3(CCH / 128, MROWS / 128), 128, SMEM_DYN>>>(
        proj_b, out);
}

// round 16
// speedup vs baseline: 1.2862x; 1.2862x over previous
#include <cuda_runtime.h>
#include <cuda_bf16.h>
#include <cuda_fp16.h>
#include <cstdint>

// ---------------------------------------------------------------------------
// Swin shifted-window attention, B=32 H=W=56 C=512 NH=16 HD=32 WS=7 SS=3
//   k0: build row-index table
//   kw: convert weights fp32 -> fp16
//   kx: convert+gather x     -> g_a_h (fp16, window-row order)
//   k1: QKV GEMM  mma.sync fp16, cp.async 6-stage -> g_qkvh (fp16)
//   k2: attention per (window, head), tensor-core FA2-style -> g_att_h
//   k3: proj GEMM (scatter-C) -> out (fp32)
//
// R15 -> R16: REVERT to the measured-best R14 GEMM shape (256 thr, 8 warps
// 4x2, warp tile 32x64, 2 CTAs/SM -- the 64x64/128-thr variant halved
// occupancy and regressed). Single change vs R14: ALL cp.async fills use
// .cg (L1 bypass). R14 filled B with .ca, which allocates fill data in L1
// and competes with the LDSM stream that dominates L1 (82.5%).
// tcgen05 unavailable (plain sm_103 ptxas target) -> mma.sync + ldmatrix.
// ---------------------------------------------------------------------------

#define BATCH   32
#define IMG     56
#define CCH     512
#define NHEAD   16
#define HD      32
#define WS      7
#define SS      3
#define NTOK    49
#define TOTWIN  2048
#define MROWS   100352
#define QKVC    1536

// scratch (device globals: allocation-free; NEVER passed from host)
__device__ int   g_rowidx[MROWS];
__device__ __half g_qkvh[(size_t)MROWS * QKVC];
__device__ __half g_a_h[(size_t)MROWS * CCH];
__device__ __half g_att_h[(size_t)MROWS * CCH];
__device__ __half g_wqkv_h[QKVC * CCH];
__device__ __half g_wp_h[CCH * CCH];

__device__ __forceinline__ uint32_t smem_u32(const void* p) {
    uint32_t a;
    asm("{ .reg .u64 t; cvta.to.shared.u64 t, %1; cvt.u32.u64 %0, t; }"
        : "=r"(a) : "l"(p));
    return a;
}
__device__ __forceinline__ uint32_t pack2h(__half a, __half b) {
    return ((uint32_t)__half_as_ushort(b) << 16) | __half_as_ushort(a);
}

#define LDSM4(r0, r1, r2, r3, addr)                                            \
    asm volatile("ldmatrix.sync.aligned.m8n8.x4.shared.b16 {%0,%1,%2,%3}, [%4];" \
                 : "=r"(r0), "=r"(r1), "=r"(r2), "=r"(r3) : "r"(addr))
#define LDSM4T(r0, r1, r2, r3, addr)                                           \
    asm volatile("ldmatrix.sync.aligned.m8n8.x4.trans.shared.b16 {%0,%1,%2,%3}, [%4];" \
                 : "=r"(r0), "=r"(r1), "=r"(r2), "=r"(r3) : "r"(addr))

#define MMA_FP16(d, a, b)                                                      \
    asm volatile("mma.sync.aligned.m16n8k16.row.col.f32.f16.f16.f32 "          \
                 "{%0,%1,%2,%3}, {%4,%5,%6,%7}, {%8,%9}, {%0,%1,%2,%3};"       \
                 : "+f"((d)[0]), "+f"((d)[1]), "+f"((d)[2]), "+f"((d)[3])      \
                 : "r"((a)[0]), "r"((a)[1]), "r"((a)[2]), "r"((a)[3]),         \
                   "r"((b)[0]), "r"((b)[1]))

__device__ __forceinline__ void cpa16_cg(uint32_t dst, const void* src) {
    asm volatile("cp.async.cg.shared.global [%0], [%1], 16;"
                 :: "r"(dst), "l"(src) : "memory");
}
#define CP_COMMIT() asm volatile("cp.async.commit_group;" ::: "memory")
#define CP_WAIT4()  asm volatile("cp.async.wait_group 4;" ::: "memory")

// ---------------------------------------------------------------------------
__global__ void build_rowidx_kernel() {
    int m = blockIdx.x * 256 + threadIdx.x;
    if (m >= MROWS) return;
    int win = m / NTOK, n = m % NTOK;
    int b  = win >> 6, wi = win & 63;
    int r = (wi >> 3) * WS + n / WS;
    int c = (wi & 7) * WS + n % WS;
    int sh = r + SS; if (sh >= IMG) sh -= IMG;
    int sw = c + SS; if (sw >= IMG) sw -= IMG;
    g_rowidx[m] = (b * IMG + sh) * IMG + sw;
}

__global__ void convert_w_kernel(const float* __restrict__ qkv_w,
                                 const float* __restrict__ proj_w) {
    int i = blockIdx.x * 256 + threadIdx.x;
    if (i < QKVC * CCH) g_wqkv_h[i] = __float2half_rn(qkv_w[i]);
    if (i < CCH * CCH)  g_wp_h[i]   = __float2half_rn(proj_w[i]);
}

// gather x through rowidx, fp16 (window-row order)
__global__ void convert_x_kernel(const float* __restrict__ x) {
    size_t i = (size_t)blockIdx.x * 256 + threadIdx.x;   // over MROWS*128
    if (i >= (size_t)MROWS * 128) return;
    int m = (int)(i >> 7);
    int c4 = (int)(i & 127) << 2;
    float4 v = *(const float4*)(x + (size_t)g_rowidx[m] * CCH + c4);
    uint2 hp;
    hp.x = pack2h(__float2half_rn(v.x), __float2half_rn(v.y));
    hp.y = pack2h(__float2half_rn(v.z), __float2half_rn(v.w));
    *(uint2*)(g_a_h + (size_t)m * CCH + c4) = hp;
}

// ---------------------------------------------------------------------------
// mma.sync fp16 GEMM: BM=BN=128, BK=32, 256 thr (8 warps 4x2, warp tile
// 32x64). cp.async 6-stage pipeline (5 in flight), 2 CTA/SM.
// Stage (16KB): A @0, B @8KB; 128 rows x 64B, chunk-swizzled:
//   phys_chunk = c ^ ((r>>1)&3) ^ ((r>>3)&1)
// All fills .cg (L1 bypass) -- L1 is the LDSM bottleneck, don't pollute it.
// QKV=true : C -> g_qkvh (fp16).  QKV=false: C -> out fp32, rowidx scatter.
// ---------------------------------------------------------------------------
#define AOFF 0
#define BOFF 8192
#define BUFB 16384
#define NSTG 6
#define NKCH 16            // 512/32
#define SMEM_DYN (NSTG * BUFB)

__device__ __forceinline__ uint32_t swz(int r, int c) {
    return (uint32_t)(r * 64 + ((c ^ ((r >> 1) & 3) ^ ((r >> 3) & 1)) << 4));
}

template <bool QKV>
__global__ __launch_bounds__(256, 2)
void gemm_mma_kernel(const float* __restrict__ bias,
                     float* __restrict__ out)
{
    extern __shared__ char smem[];
    const uint32_t sbase = smem_u32(smem);
    const int tid = threadIdx.x;
    const int lane = tid & 31, warp = tid >> 5;
    const int wm = warp >> 1, wn = warp & 1;
    const int bm = blockIdx.y * 128, bn = blockIdx.x * 128;

    const __half* __restrict__ Aw = QKV ? g_a_h : g_att_h;
    const __half* __restrict__ Bw = QKV ? g_wqkv_h : g_wp_h;

    const int lrow = tid >> 1, half = tid & 1;
    const size_t ga = (size_t)(bm + lrow) * CCH + half * 16;
    const size_t gb = (size_t)(bn + lrow) * CCH + half * 16;
    const uint32_t st0 = swz(lrow, 2 * half);
    const uint32_t st1 = swz(lrow, 2 * half + 1);

    auto issue = [&](int kt, int s) {
        uint32_t b = sbase + s * BUFB;
        const __half* p;
        p = Aw + ga + kt * 32; cpa16_cg(b + AOFF + st0, p); cpa16_cg(b + AOFF + st1, p + 8);
        p = Bw + gb + kt * 32; cpa16_cg(b + BOFF + st0, p); cpa16_cg(b + BOFF + st1, p + 8);
        CP_COMMIT();
    };

    uint32_t aoff_[2][2], boff[2][4];
#pragma unroll
    for (int s = 0; s < 2; s++) {
#pragma unroll
        for (int mt = 0; mt < 2; mt++) {
            int r = wm * 32 + mt * 16 + (lane & 15);
            aoff_[s][mt] = swz(r, 2 * s + (lane >> 4));
        }
#pragma unroll
        for (int p = 0; p < 4; p++) {
            int n = wn * 64 + p * 16 + ((lane >> 4) & 1) * 8 + (lane & 7);
            boff[s][p] = swz(n, 2 * s + ((lane >> 3) & 1));
        }
    }

    float acc[2][8][4];
#pragma unroll
    for (int mt = 0; mt < 2; mt++)
#pragma unroll
        for (int nt = 0; nt < 8; nt++)
#pragma unroll
            for (int j = 0; j < 4; j++) acc[mt][nt][j] = 0.f;

    auto compute = [&](uint32_t bb) {
#pragma unroll
        for (int s = 0; s < 2; s++) {
            uint32_t ah[2][4], bh_[8][2];
#pragma unroll
            for (int mt = 0; mt < 2; mt++)
                LDSM4(ah[mt][0], ah[mt][1], ah[mt][2], ah[mt][3],
                      bb + AOFF + aoff_[s][mt]);
#pragma unroll
            for (int p = 0; p < 4; p++) {
                uint32_t t0, t1, t2, t3;
                LDSM4(t0, t1, t2, t3, bb + BOFF + boff[s][p]);
                bh_[2 * p][0] = t0; bh_[2 * p][1] = t1;
                bh_[2 * p + 1][0] = t2; bh_[2 * p + 1][1] = t3;
            }
#pragma unroll
            for (int mt = 0; mt < 2; mt++)
#pragma unroll
                for (int nt = 0; nt < 8; nt++)
                    MMA_FP16(acc[mt][nt], ah[mt], bh_[nt]);
        }
    };

    // ---- pipeline: 5 chunks in flight, 6 stages ----
    issue(0, 0); issue(1, 1); issue(2, 2); issue(3, 3); issue(4, 4);
    for (int kt = 0; kt < NKCH; kt++) {
        CP_WAIT4();                 // 5 groups pending at top -> kt complete
        __syncthreads();            // all warps done with stage being reused
        if (kt + 5 < NKCH) issue(kt + 5, (kt + 5) % NSTG);
        else               CP_COMMIT();     // keep group count uniform
        compute(sbase + (kt % NSTG) * BUFB);
    }

    // ---- epilogue ----
#pragma unroll
    for (int mt = 0; mt < 2; mt++) {
        int mr = bm + wm * 32 + mt * 16 + (lane >> 2);
        const int cbase = bn + wn * 64 + 2 * (lane & 3);
        if (QKV) {
            size_t r0 = (size_t)mr * QKVC, r1 = (size_t)(mr + 8) * QKVC;
#pragma unroll
            for (int nt = 0; nt < 8; nt++) {
                float2 bb = *(const float2*)(bias + cbase + nt * 8);
                uint32_t u0 = pack2h(__float2half_rn(acc[mt][nt][0] + bb.x),
                                     __float2half_rn(acc[mt][nt][1] + bb.y));
                uint32_t u1 = pack2h(__float2half_rn(acc[mt][nt][2] + bb.x),
                                     __float2half_rn(acc[mt][nt][3] + bb.y));
                *(uint32_t*)(g_qkvh + r0 + cbase + nt * 8) = u0;
                *(uint32_t*)(g_qkvh + r1 + cbase + nt * 8) = u1;
            }
        } else {
            size_t r0 = (size_t)g_rowidx[mr] * CCH;
            size_t r1 = (size_t)g_rowidx[mr + 8] * CCH;
            float* p0 = out + r0 + cbase;
            float* p1 = out + r1 + cbase;
#pragma unroll
            for (int nt = 0; nt < 8; nt++) {
                float2 bb = *(const float2*)(bias + cbase + nt * 8);
                float2 v0, v1;
                v0.x = acc[mt][nt][0] + bb.x; v0.y = acc[mt][nt][1] + bb.y;
                v1.x = acc[mt][nt][2] + bb.x; v1.y = acc[mt][nt][3] + bb.y;
                *(float2*)(p0 + nt * 8) = v0;
                *(float2*)(p1 + nt * 8) = v1;
            }
        }
    }
}

// ---------------------------------------------------------------------------
// Attention: block = (window, head), 128 thr = 4 warps, warp = one m16 tile.
// q/k/v fp16 in smem (row stride 40 halves = 80B, conflict-free ldmatrix).
// S via mma fragments, in-register softmax (quad shfl_xor), P repacked to
// A-frags in registers, PV via trans ldmatrix. Bias matrix (rel-pos + shift
// mask, cols 49-55 = -1e30, pad rows 0) built per block. (unchanged)
// ---------------------------------------------------------------------------
#define ASTR 40

__global__ __launch_bounds__(128)
void attn_kernel(const float* __restrict__ rel)
{
    const int win = blockIdx.x >> 4;
    const int h   = blockIdx.x & 15;
    const int tid = threadIdx.x;
    const int lane = tid & 31, warp = tid >> 5;

    __shared__ __align__(16) __half qs[64 * ASTR];
    __shared__ __align__(16) __half ks[64 * ASTR];
    __shared__ __align__(16) __half vs[64 * ASTR];
    __shared__ float bm_s[64 * 56];
    __shared__ float tb[169];
    __shared__ int   lab[NTOK];

    for (int i = tid; i < 169; i += 128)
        tb[i] = rel[i * NHEAD + h];
    if (tid < NTOK) {
        int wi = win & 63;
        int r = (wi >> 3) * WS + tid / WS;
        int c = (wi & 7) * WS + tid % WS;
        int rh = (r < IMG - WS) ? 0 : (r < IMG - SS ? 1 : 2);
        int rw = (c < IMG - WS) ? 0 : (c < IMG - SS ? 1 : 2);
        lab[tid] = rh * 3 + rw;
    }
    const size_t base = (size_t)(win * NTOK) * QKVC + h * HD;
    for (int e = tid; e < NTOK * 8; e += 128) {
        int n = e >> 3, c4 = (e & 7) * 4;
        const __half* p = g_qkvh + base + (size_t)n * QKVC + c4;
        *(uint2*)&qs[n * ASTR + c4] = *(const uint2*)(p);
        *(uint2*)&ks[n * ASTR + c4] = *(const uint2*)(p + 512);
        *(uint2*)&vs[n * ASTR + c4] = *(const uint2*)(p + 1024);
    }
    for (int e = tid; e < 15 * 8; e += 128) {     // zero pad rows 49..63
        int n = NTOK + (e >> 3), c4 = (e & 7) * 4;
        *(uint2*)&qs[n * ASTR + c4] = make_uint2(0, 0);
        *(uint2*)&ks[n * ASTR + c4] = make_uint2(0, 0);
        *(uint2*)&vs[n * ASTR + c4] = make_uint2(0, 0);
    }
    __syncthreads();

    for (int idx = tid; idx < 64 * 56; idx += 128) {
        int r = idx / 56, c = idx % 56;
        float v;
        if (r >= NTOK)      v = 0.0f;
        else if (c >= NTOK) v = -1e30f;
        else {
            int rr = r / WS, rm = r % WS, cr = c / WS, cm = c % WS;
            v = tb[(rr - cr + 6) * 13 + (rm - cm + 6)];
            if (lab[r] != lab[c]) v -= 100.0f;
        }
        bm_s[idx] = v;
    }
    __syncthreads();

    const int m0 = warp * 16;
    const int g = lane >> 2, t = lane & 3;
    const int lane15 = lane & 15, lhalf = lane >> 4;
    const uint32_t qb = smem_u32(qs), kb = smem_u32(ks), vb = smem_u32(vs);

    uint32_t af[2][4];
    {
        uint32_t aa = qb + ((m0 + lane15) * ASTR + lhalf * 8) * 2;
        LDSM4(af[0][0], af[0][1], af[0][2], af[0][3], aa);
        LDSM4(af[1][0], af[1][1], af[1][2], af[1][3], aa + 32);
    }

    float sacc[7][4];
#pragma unroll
    for (int j = 0; j < 7; j++)
#pragma unroll
        for (int i = 0; i < 4; i++) sacc[j][i] = 0.f;

#pragma unroll
    for (int nc = 0; nc < 4; nc++) {
        uint32_t ka = kb + ((nc * 16 + lane15) * ASTR + lhalf * 8) * 2;
#pragma unroll
        for (int kk = 0; kk < 2; kk++) {
            uint32_t r0, r1, r2, r3;
            LDSM4(r0, r1, r2, r3, ka + kk * 32);
            uint32_t blo[2] = { r0, r2 };
            uint32_t bhi[2] = { r1, r3 };
            MMA_FP16(sacc[2 * nc], af[kk], blo);
            if (2 * nc + 1 < 7) MMA_FP16(sacc[2 * nc + 1], af[kk], bhi);
        }
    }

    const float scale = 0.17677669529663687f;   // 32^-0.5
    const int r_lo = m0 + g, r_hi = m0 + g + 8;
#pragma unroll
    for (int j = 0; j < 7; j++) {
        int c0 = j * 8 + 2 * t;
        sacc[j][0] = sacc[j][0] * scale + bm_s[r_lo * 56 + c0];
        sacc[j][1] = sacc[j][1] * scale + bm_s[r_lo * 56 + c0 + 1];
        sacc[j][2] = sacc[j][2] * scale + bm_s[r_hi * 56 + c0];
        sacc[j][3] = sacc[j][3] * scale + bm_s[r_hi * 56 + c0 + 1];
    }
    float mlo = -1e30f, mhi = -1e30f;
#pragma unroll
    for (int j = 0; j < 7; j++) {
        mlo = fmaxf(mlo, fmaxf(sacc[j][0], sacc[j][1]));
        mhi = fmaxf(mhi, fmaxf(sacc[j][2], sacc[j][3]));
    }
    mlo = fmaxf(mlo, __shfl_xor_sync(0xffffffffu, mlo, 1));
    mlo = fmaxf(mlo, __shfl_xor_sync(0xffffffffu, mlo, 2));
    mhi = fmaxf(mhi, __shfl_xor_sync(0xffffffffu, mhi, 1));
    mhi = fmaxf(mhi, __shfl_xor_sync(0xffffffffu, mhi, 2));
    float slo = 0.f, shi = 0.f;
#pragma unroll
    for (int j = 0; j < 7; j++) {
        sacc[j][0] = __expf(sacc[j][0] - mlo);
        sacc[j][1] = __expf(sacc[j][1] - mlo);
        sacc[j][2] = __expf(sacc[j][2] - mhi);
        sacc[j][3] = __expf(sacc[j][3] - mhi);
        slo += sacc[j][0] + sacc[j][1];
        shi += sacc[j][2] + sacc[j][3];
    }
    slo += __shfl_xor_sync(0xffffffffu, slo, 1);
    slo += __shfl_xor_sync(0xffffffffu, slo, 2);
    shi += __shfl_xor_sync(0xffffffffu, shi, 1);
    shi += __shfl_xor_sync(0xffffffffu, shi, 2);
    const float ilo = 1.0f / slo, ihi = 1.0f / shi;

    uint32_t pf[7][2];
#pragma unroll
    for (int j = 0; j < 7; j++) {
        pf[j][0] = pack2h(__float2half_rn(sacc[j][0] * ilo),
                          __float2half_rn(sacc[j][1] * ilo));
        pf[j][1] = pack2h(__float2half_rn(sacc[j][2] * ihi),
                          __float2half_rn(sacc[j][3] * ihi));
    }

    float oacc[4][4];
#pragma unroll
    for (int nt = 0; nt < 4; nt++)
#pragma unroll
        for (int i = 0; i < 4; i++) oacc[nt][i] = 0.f;

    const int grp = lane >> 3, lr8 = lane & 7;
    const int vrow_off = lr8 + ((grp & 1) ? 8 : 0);
    const int vcol_off = (grp >= 2) ? 8 : 0;
#pragma unroll
    for (int kk = 0; kk < 4; kk++) {
        uint32_t a[4];
        a[0] = pf[2 * kk][0];
        a[1] = pf[2 * kk][1];
        a[2] = (2 * kk + 1 < 7) ? pf[2 * kk + 1][0] : 0u;
        a[3] = (2 * kk + 1 < 7) ? pf[2 * kk + 1][1] : 0u;
#pragma unroll
        for (int nv = 0; nv < 2; nv++) {
            uint32_t va = vb + ((kk * 16 + vrow_off) * ASTR + nv * 16 + vcol_off) * 2;
            uint32_t r0, r1, r2, r3;
            LDSM4T(r0, r1, r2, r3, va);
            uint32_t b0[2] = { r0, r1 };
            uint32_t b1[2] = { r2, r3 };
            MMA_FP16(oacc[2 * nv], a, b0);
            MMA_FP16(oacc[2 * nv + 1], a, b1);
        }
    }

    const size_t obase = (size_t)(win * NTOK) * CCH + h * HD;
    if (r_lo < NTOK) {
        size_t rb = obase + (size_t)r_lo * CCH;
#pragma unroll
        for (int nt = 0; nt < 4; nt++) {
            int col = nt * 8 + 2 * t;
            *(uint32_t*)(g_att_h + rb + col) =
                pack2h(__float2half_rn(oacc[nt][0]), __float2half_rn(oacc[nt][1]));
        }
    }
    if (r_hi < NTOK) {
        size_t rb = obase + (size_t)r_hi * CCH;
#pragma unroll
        for (int nt = 0; nt < 4; nt++) {
            int col = nt * 8 + 2 * t;
            *(uint32_t*)(g_att_h + rb + col) =
                pack2h(__float2half_rn(oacc[nt][2]), __float2half_rn(oacc[nt][3]));
        }
    }
}

// ---------------------------------------------------------------------------
extern "C" void kernel_launch(void* const* d_in, const int* in_sizes, int n_in,
                              void* d_out, int out_size)
{
    const float* x      = (const float*)d_in[0];
    const float* qkv_w  = (const float*)d_in[1];
    const float* qkv_b  = (const float*)d_in[2];
    const float* proj_w = (const float*)d_in[3];
    const float* proj_b = (const float*)d_in[4];
    const float* rel    = (const float*)d_in[5];
    float* out = (float*)d_out;

    cudaFuncSetAttribute(gemm_mma_kernel<true>,
                         cudaFuncAttributeMaxDynamicSharedMemorySize, SMEM_DYN);
    cudaFuncSetAttribute(gemm_mma_kernel<false>,
                         cudaFuncAttributeMaxDynamicSharedMemorySize, SMEM_DYN);

    build_rowidx_kernel<<<(MROWS + 255) / 256, 256>>>();
    convert_w_kernel<<<(QKVC * CCH + 255) / 256, 256>>>(qkv_w, proj_w);
    convert_x_kernel<<<(int)(((size_t)MROWS * 128 + 255) / 256), 256>>>(x);

    // QKV: M=100352, N=1536 -> fp16 g_qkvh
    gemm_mma_kernel<true><<<dim3(QKVC / 128, MROWS / 128), 256, SMEM_DYN>>>(
        qkv_b, nullptr);

    attn_kernel<<<TOTWIN * NHEAD, 128>>>(rel);

    // proj: M=100352, N=512 (A = g_att_h, scatter-C to out)
    gemm_mma_kernel<false><<<dim3(CCH / 128, MROWS / 128), 256, SMEM_DYN>>>(
        proj_b, out);
}

// round 17
// speedup vs baseline: 1.3424x; 1.0437x over previous
#include <cuda_runtime.h>
#include <cuda_bf16.h>
#include <cuda_fp16.h>
#include <cstdint>

// ---------------------------------------------------------------------------
// Swin shifted-window attention, B=32 H=W=56 C=512 NH=16 HD=32 WS=7 SS=3
//   k0: build row-index table
//   kw: convert weights fp32 -> fp16
//   kb: precompute bias matrices (4 window types x 16 heads, 64x56 fp32)
//   kx: convert+gather x     -> g_a_h (fp16, window-row order)
//   k1: QKV GEMM  mma.sync fp16, BK=64, cp.async 3-stage -> g_qkvh (fp16)
//   k2: attention per (window, head), tensor-core FA2-style -> g_att_h
//   k3: proj GEMM (scatter-C) -> out (fp32)
//
// R16 -> R17: GEMM was barrier/wait-bound (tensor 52%, L1 57%, issue 15% --
// nothing saturated). BK 32 -> 64: half the wait+syncthreads barriers,
// double the MMA run per sync. 128B-row swizzle chunk c ^= (r&7); step
// offsets via addr(s) = addr(0) ^ (s<<5). Attention bias matrix hoisted to
// a precompute kernel (depends only on head x 4 window types, 916KB, L2).
// tcgen05 unavailable (plain sm_103 ptxas target) -> mma.sync + ldmatrix.
// ---------------------------------------------------------------------------

#define BATCH   32
#define IMG     56
#define CCH     512
#define NHEAD   16
#define HD      32
#define WS      7
#define SS      3
#define NTOK    49
#define TOTWIN  2048
#define MROWS   100352
#define QKVC    1536

// scratch (device globals: allocation-free; NEVER passed from host)
__device__ int   g_rowidx[MROWS];
__device__ __half g_qkvh[(size_t)MROWS * QKVC];
__device__ __half g_a_h[(size_t)MROWS * CCH];
__device__ __half g_att_h[(size_t)MROWS * CCH];
__device__ __half g_wqkv_h[QKVC * CCH];
__device__ __half g_wp_h[CCH * CCH];
__device__ float  g_biasm[4][NHEAD][64 * 56];   // [wintype][head][r][c]

__device__ __forceinline__ uint32_t smem_u32(const void* p) {
    uint32_t a;
    asm("{ .reg .u64 t; cvta.to.shared.u64 t, %1; cvt.u32.u64 %0, t; }"
        : "=r"(a) : "l"(p));
    return a;
}
__device__ __forceinline__ uint32_t pack2h(__half a, __half b) {
    return ((uint32_t)__half_as_ushort(b) << 16) | __half_as_ushort(a);
}

#define LDSM4(r0, r1, r2, r3, addr)                                            \
    asm volatile("ldmatrix.sync.aligned.m8n8.x4.shared.b16 {%0,%1,%2,%3}, [%4];" \
                 : "=r"(r0), "=r"(r1), "=r"(r2), "=r"(r3) : "r"(addr))
#define LDSM4T(r0, r1, r2, r3, addr)                                           \
    asm volatile("ldmatrix.sync.aligned.m8n8.x4.trans.shared.b16 {%0,%1,%2,%3}, [%4];" \
                 : "=r"(r0), "=r"(r1), "=r"(r2), "=r"(r3) : "r"(addr))

#define MMA_FP16(d, a, b)                                                      \
    asm volatile("mma.sync.aligned.m16n8k16.row.col.f32.f16.f16.f32 "          \
                 "{%0,%1,%2,%3}, {%4,%5,%6,%7}, {%8,%9}, {%0,%1,%2,%3};"       \
                 : "+f"((d)[0]), "+f"((d)[1]), "+f"((d)[2]), "+f"((d)[3])      \
                 : "r"((a)[0]), "r"((a)[1]), "r"((a)[2]), "r"((a)[3]),         \
                   "r"((b)[0]), "r"((b)[1]))

__device__ __forceinline__ void cpa16_cg(uint32_t dst, const void* src) {
    asm volatile("cp.async.cg.shared.global [%0], [%1], 16;"
                 :: "r"(dst), "l"(src) : "memory");
}
#define CP_COMMIT() asm volatile("cp.async.commit_group;" ::: "memory")
#define CP_WAIT1()  asm volatile("cp.async.wait_group 1;" ::: "memory")

// ---------------------------------------------------------------------------
__global__ void build_rowidx_kernel() {
    int m = blockIdx.x * 256 + threadIdx.x;
    if (m >= MROWS) return;
    int win = m / NTOK, n = m % NTOK;
    int b  = win >> 6, wi = win & 63;
    int r = (wi >> 3) * WS + n / WS;
    int c = (wi & 7) * WS + n % WS;
    int sh = r + SS; if (sh >= IMG) sh -= IMG;
    int sw = c + SS; if (sw >= IMG) sw -= IMG;
    g_rowidx[m] = (b * IMG + sh) * IMG + sw;
}

__global__ void convert_w_kernel(const float* __restrict__ qkv_w,
                                 const float* __restrict__ proj_w) {
    int i = blockIdx.x * 256 + threadIdx.x;
    if (i < QKVC * CCH) g_wqkv_h[i] = __float2half_rn(qkv_w[i]);
    if (i < CCH * CCH)  g_wp_h[i]   = __float2half_rn(proj_w[i]);
}

// One block per (wintype, head): rel-pos bias + shift mask, 64x56 fp32.
// type bit0: window row-block is the last one (wh==7); bit1: same for cols.
__global__ void build_bias_kernel(const float* __restrict__ rel) {
    const int type = blockIdx.x >> 4, h = blockIdx.x & 15;
    const int tid = threadIdx.x;
    __shared__ float tb[169];
    __shared__ int   lab[NTOK];
    for (int i = tid; i < 169; i += 256) tb[i] = rel[i * NHEAD + h];
    if (tid < NTOK) {
        int lr = tid / WS, lc = tid % WS;
        int rh = (type & 1) ? (lr < 4 ? 1 : 2) : 0;   // global r=49+lr: <53 ? 1 : 2
        int rw = (type & 2) ? (lc < 4 ? 1 : 2) : 0;
        lab[tid] = rh * 3 + rw;
    }
    __syncthreads();
    float* dst = g_biasm[type][h];
    for (int idx = tid; idx < 64 * 56; idx += 256) {
        int r = idx / 56, c = idx % 56;
        float v;
        if (r >= NTOK)      v = 0.0f;
        else if (c >= NTOK) v = -1e30f;
        else {
            int rr = r / WS, rm = r % WS, cr = c / WS, cm = c % WS;
            v = tb[(rr - cr + 6) * 13 + (rm - cm + 6)];
            if (lab[r] != lab[c]) v -= 100.0f;
        }
        dst[idx] = v;
    }
}

// gather x through rowidx, fp16 (window-row order)
__global__ void convert_x_kernel(const float* __restrict__ x) {
    size_t i = (size_t)blockIdx.x * 256 + threadIdx.x;   // over MROWS*128
    if (i >= (size_t)MROWS * 128) return;
    int m = (int)(i >> 7);
    int c4 = (int)(i & 127) << 2;
    float4 v = *(const float4*)(x + (size_t)g_rowidx[m] * CCH + c4);
    uint2 hp;
    hp.x = pack2h(__float2half_rn(v.x), __float2half_rn(v.y));
    hp.y = pack2h(__float2half_rn(v.z), __float2half_rn(v.w));
    *(uint2*)(g_a_h + (size_t)m * CCH + c4) = hp;
}

// ---------------------------------------------------------------------------
// mma.sync fp16 GEMM: BM=BN=128, BK=64, 256 thr (8 warps 4x2, warp tile
// 32x64). cp.async 3-stage pipeline (2 chunks in flight), 2 CTA/SM.
// Stage (32KB): A @0, B @16KB; 128 rows x 128B; swizzle: 16B-chunk
//   phys = c ^ (r & 7)  (c in [0,8)). ldmatrix step s: addr ^ (s<<5).
// All fills .cg (L1 bypass). QKV=true: C -> g_qkvh fp16; else fp32 scatter.
// ---------------------------------------------------------------------------
#define AOFF 0
#define BOFF 16384
#define BUFB 32768
#define NSTG 3
#define NKCH 8             // 512/64
#define SMEM_DYN (NSTG * BUFB)

__device__ __forceinline__ uint32_t swz64(int r, int c) {
    return (uint32_t)(r * 128 + ((c ^ (r & 7)) << 4));
}

template <bool QKV>
__global__ __launch_bounds__(256, 2)
void gemm_mma_kernel(const float* __restrict__ bias,
                     float* __restrict__ out)
{
    extern __shared__ char smem[];
    const uint32_t sbase = smem_u32(smem);
    const int tid = threadIdx.x;
    const int lane = tid & 31, warp = tid >> 5;
    const int wm = warp >> 1, wn = warp & 1;
    const int bm = blockIdx.y * 128, bn = blockIdx.x * 128;

    const __half* __restrict__ Aw = QKV ? g_a_h : g_att_h;
    const __half* __restrict__ Bw = QKV ? g_wqkv_h : g_wp_h;

    // loader: thread t -> row t/2, k-half t&1 (32 halves = 4x16B chunks)
    const int lrow = tid >> 1, half = tid & 1;
    const size_t ga = (size_t)(bm + lrow) * CCH + half * 32;
    const size_t gb = (size_t)(bn + lrow) * CCH + half * 32;
    uint32_t sto[4];
#pragma unroll
    for (int c = 0; c < 4; c++) sto[c] = swz64(lrow, half * 4 + c);

    auto issue = [&](int kt, int s) {
        uint32_t b = sbase + s * BUFB;
        const __half* pa = Aw + ga + kt * 64;
        const __half* pb = Bw + gb + kt * 64;
#pragma unroll
        for (int c = 0; c < 4; c++) {
            cpa16_cg(b + AOFF + sto[c], pa + c * 8);
            cpa16_cg(b + BOFF + sto[c], pb + c * 8);
        }
        CP_COMMIT();
    };

    // ldmatrix base offsets (step s applied as ^ (s<<5))
    const int lane15 = lane & 15;
    uint32_t aoff0[2], boff0[4];
#pragma unroll
    for (int mt = 0; mt < 2; mt++) {
        int r = wm * 32 + mt * 16 + lane15;
        aoff0[mt] = swz64(r, lane >> 4);
    }
#pragma unroll
    for (int p = 0; p < 4; p++) {
        int n = wn * 64 + p * 16 + ((lane >> 4) & 1) * 8 + (lane & 7);
        boff0[p] = swz64(n, (lane >> 3) & 1);
    }

    float acc[2][8][4];
#pragma unroll
    for (int mt = 0; mt < 2; mt++)
#pragma unroll
        for (int nt = 0; nt < 8; nt++)
#pragma unroll
            for (int j = 0; j < 4; j++) acc[mt][nt][j] = 0.f;

    auto compute = [&](uint32_t bb) {
#pragma unroll
        for (int s = 0; s < 4; s++) {
            const uint32_t sx = (uint32_t)(s << 5);
            uint32_t ah[2][4], bh_[8][2];
#pragma unroll
            for (int mt = 0; mt < 2; mt++)
                LDSM4(ah[mt][0], ah[mt][1], ah[mt][2], ah[mt][3],
                      (bb + AOFF + aoff0[mt]) ^ sx);
#pragma unroll
            for (int p = 0; p < 4; p++) {
                uint32_t t0, t1, t2, t3;
                LDSM4(t0, t1, t2, t3, (bb + BOFF + boff0[p]) ^ sx);
                bh_[2 * p][0] = t0; bh_[2 * p][1] = t1;
                bh_[2 * p + 1][0] = t2; bh_[2 * p + 1][1] = t3;
            }
#pragma unroll
            for (int mt = 0; mt < 2; mt++)
#pragma unroll
                for (int nt = 0; nt < 8; nt++)
                    MMA_FP16(acc[mt][nt], ah[mt], bh_[nt]);
        }
    };

    // ---- pipeline: 2 chunks in flight, 3 stages ----
    issue(0, 0); issue(1, 1);
    for (int kt = 0; kt < NKCH; kt++) {
        CP_WAIT1();                 // 2 groups pending at top -> kt complete
        __syncthreads();            // all warps done with stage being reused
        if (kt + 2 < NKCH) issue(kt + 2, (kt + 2) % NSTG);
        else               CP_COMMIT();     // keep group count uniform
        compute(sbase + (kt % NSTG) * BUFB);
    }

    // ---- epilogue ----
#pragma unroll
    for (int mt = 0; mt < 2; mt++) {
        int mr = bm + wm * 32 + mt * 16 + (lane >> 2);
        const int cbase = bn + wn * 64 + 2 * (lane & 3);
        if (QKV) {
            size_t r0 = (size_t)mr * QKVC, r1 = (size_t)(mr + 8) * QKVC;
#pragma unroll
            for (int nt = 0; nt < 8; nt++) {
                float2 bb = *(const float2*)(bias + cbase + nt * 8);
                uint32_t u0 = pack2h(__float2half_rn(acc[mt][nt][0] + bb.x),
                                     __float2half_rn(acc[mt][nt][1] + bb.y));
                uint32_t u1 = pack2h(__float2half_rn(acc[mt][nt][2] + bb.x),
                                     __float2half_rn(acc[mt][nt][3] + bb.y));
                *(uint32_t*)(g_qkvh + r0 + cbase + nt * 8) = u0;
                *(uint32_t*)(g_qkvh + r1 + cbase + nt * 8) = u1;
            }
        } else {
            size_t r0 = (size_t)g_rowidx[mr] * CCH;
            size_t r1 = (size_t)g_rowidx[mr + 8] * CCH;
            float* p0 = out + r0 + cbase;
            float* p1 = out + r1 + cbase;
#pragma unroll
            for (int nt = 0; nt < 8; nt++) {
                float2 bb = *(const float2*)(bias + cbase + nt * 8);
                float2 v0, v1;
                v0.x = acc[mt][nt][0] + bb.x; v0.y = acc[mt][nt][1] + bb.y;
                v1.x = acc[mt][nt][2] + bb.x; v1.y = acc[mt][nt][3] + bb.y;
                *(float2*)(p0 + nt * 8) = v0;
                *(float2*)(p1 + nt * 8) = v1;
            }
        }
    }
}

// ---------------------------------------------------------------------------
// Attention: block = (window, head), 128 thr = 4 warps, warp = one m16 tile.
// q/k/v fp16 in smem (row stride 40 halves = 80B, conflict-free ldmatrix).
// Bias matrix now COPIED from g_biasm (precomputed per head x window-type).
// S via mma fragments, in-register softmax, P repacked to A-frags, PV via
// trans ldmatrix.
// ---------------------------------------------------------------------------
#define ASTR 40

__global__ __launch_bounds__(128)
void attn_kernel()
{
    const int win = blockIdx.x >> 4;
    const int h   = blockIdx.x & 15;
    const int tid = threadIdx.x;
    const int lane = tid & 31, warp = tid >> 5;

    __shared__ __align__(16) __half qs[64 * ASTR];
    __shared__ __align__(16) __half ks[64 * ASTR];
    __shared__ __align__(16) __half vs[64 * ASTR];
    __shared__ __align__(16) float bm_s[64 * 56];

    // bias matrix: straight float4 copy from precomputed table
    {
        const int wi = win & 63;
        const int type = ((wi >> 3) == 7 ? 1 : 0) | ((wi & 7) == 7 ? 2 : 0);
        const float4* src = (const float4*)g_biasm[type][h];
        float4* dst = (float4*)bm_s;
        for (int i = tid; i < 64 * 56 / 4; i += 128) dst[i] = src[i];
    }
    const size_t base = (size_t)(win * NTOK) * QKVC + h * HD;
    for (int e = tid; e < NTOK * 8; e += 128) {
        int n = e >> 3, c4 = (e & 7) * 4;
        const __half* p = g_qkvh + base + (size_t)n * QKVC + c4;
        *(uint2*)&qs[n * ASTR + c4] = *(const uint2*)(p);
        *(uint2*)&ks[n * ASTR + c4] = *(const uint2*)(p + 512);
        *(uint2*)&vs[n * ASTR + c4] = *(const uint2*)(p + 1024);
    }
    for (int e = tid; e < 15 * 8; e += 128) {     // zero pad rows 49..63
        int n = NTOK + (e >> 3), c4 = (e & 7) * 4;
        *(uint2*)&qs[n * ASTR + c4] = make_uint2(0, 0);
        *(uint2*)&ks[n * ASTR + c4] = make_uint2(0, 0);
        *(uint2*)&vs[n * ASTR + c4] = make_uint2(0, 0);
    }
    __syncthreads();

    const int m0 = warp * 16;
    const int g = lane >> 2, t = lane & 3;
    const int lane15 = lane & 15, lhalf = lane >> 4;
    const uint32_t qb = smem_u32(qs), kb = smem_u32(ks), vb = smem_u32(vs);

    uint32_t af[2][4];
    {
        uint32_t aa = qb + ((m0 + lane15) * ASTR + lhalf * 8) * 2;
        LDSM4(af[0][0], af[0][1], af[0][2], af[0][3], aa);
        LDSM4(af[1][0], af[1][1], af[1][2], af[1][3], aa + 32);
    }

    float sacc[7][4];
#pragma unroll
    for (int j = 0; j < 7; j++)
#pragma unroll
        for (int i = 0; i < 4; i++) sacc[j][i] = 0.f;

#pragma unroll
    for (int nc = 0; nc < 4; nc++) {
        uint32_t ka = kb + ((nc * 16 + lane15) * ASTR + lhalf * 8) * 2;
#pragma unroll
        for (int kk = 0; kk < 2; kk++) {
            uint32_t r0, r1, r2, r3;
            LDSM4(r0, r1, r2, r3, ka + kk * 32);
            uint32_t blo[2] = { r0, r2 };
            uint32_t bhi[2] = { r1, r3 };
            MMA_FP16(sacc[2 * nc], af[kk], blo);
            if (2 * nc + 1 < 7) MMA_FP16(sacc[2 * nc + 1], af[kk], bhi);
        }
    }

    const float scale = 0.17677669529663687f;   // 32^-0.5
    const int r_lo = m0 + g, r_hi = m0 + g + 8;
#pragma unroll
    for (int j = 0; j < 7; j++) {
        int c0 = j * 8 + 2 * t;
        sacc[j][0] = sacc[j][0] * scale + bm_s[r_lo * 56 + c0];
        sacc[j][1] = sacc[j][1] * scale + bm_s[r_lo * 56 + c0 + 1];
        sacc[j][2] = sacc[j][2] * scale + bm_s[r_hi * 56 + c0];
        sacc[j][3] = sacc[j][3] * scale + bm_s[r_hi * 56 + c0 + 1];
    }
    float mlo = -1e30f, mhi = -1e30f;
#pragma unroll
    for (int j = 0; j < 7; j++) {
        mlo = fmaxf(mlo, fmaxf(sacc[j][0], sacc[j][1]));
        mhi = fmaxf(mhi, fmaxf(sacc[j][2], sacc[j][3]));
    }
    mlo = fmaxf(mlo, __shfl_xor_sync(0xffffffffu, mlo, 1));
    mlo = fmaxf(mlo, __shfl_xor_sync(0xffffffffu, mlo, 2));
    mhi = fmaxf(mhi, __shfl_xor_sync(0xffffffffu, mhi, 1));
    mhi = fmaxf(mhi, __shfl_xor_sync(0xffffffffu, mhi, 2));
    float slo = 0.f, shi = 0.f;
#pragma unroll
    for (int j = 0; j < 7; j++) {
        sacc[j][0] = __expf(sacc[j][0] - mlo);
        sacc[j][1] = __expf(sacc[j][1] - mlo);
        sacc[j][2] = __expf(sacc[j][2] - mhi);
        sacc[j][3] = __expf(sacc[j][3] - mhi);
        slo += sacc[j][0] + sacc[j][1];
        shi += sacc[j][2] + sacc[j][3];
    }
    slo += __shfl_xor_sync(0xffffffffu, slo, 1);
    slo += __shfl_xor_sync(0xffffffffu, slo, 2);
    shi += __shfl_xor_sync(0xffffffffu, shi, 1);
    shi += __shfl_xor_sync(0xffffffffu, shi, 2);
    const float ilo = 1.0f / slo, ihi = 1.0f / shi;

    uint32_t pf[7][2];
#pragma unroll
    for (int j = 0; j < 7; j++) {
        pf[j][0] = pack2h(__float2half_rn(sacc[j][0] * ilo),
                          __float2half_rn(sacc[j][1] * ilo));
        pf[j][1] = pack2h(__float2half_rn(sacc[j][2] * ihi),
                          __float2half_rn(sacc[j][3] * ihi));
    }

    float oacc[4][4];
#pragma unroll
    for (int nt = 0; nt < 4; nt++)
#pragma unroll
        for (int i = 0; i < 4; i++) oacc[nt][i] = 0.f;

    const int grp = lane >> 3, lr8 = lane & 7;
    const int vrow_off = lr8 + ((grp & 1) ? 8 : 0);
    const int vcol_off = (grp >= 2) ? 8 : 0;
#pragma unroll
    for (int kk = 0; kk < 4; kk++) {
        uint32_t a[4];
        a[0] = pf[2 * kk][0];
        a[1] = pf[2 * kk][1];
        a[2] = (2 * kk + 1 < 7) ? pf[2 * kk + 1][0] : 0u;
        a[3] = (2 * kk + 1 < 7) ? pf[2 * kk + 1][1] : 0u;
#pragma unroll
        for (int nv = 0; nv < 2; nv++) {
            uint32_t va = vb + ((kk * 16 + vrow_off) * ASTR + nv * 16 + vcol_off) * 2;
            uint32_t r0, r1, r2, r3;
            LDSM4T(r0, r1, r2, r3, va);
            uint32_t b0[2] = { r0, r1 };
            uint32_t b1[2] = { r2, r3 };
            MMA_FP16(oacc[2 * nv], a, b0);
            MMA_FP16(oacc[2 * nv + 1], a, b1);
        }
    }

    const size_t obase = (size_t)(win * NTOK) * CCH + h * HD;
    if (r_lo < NTOK) {
        size_t rb = obase + (size_t)r_lo * CCH;
#pragma unroll
        for (int nt = 0; nt < 4; nt++) {
            int col = nt * 8 + 2 * t;
            *(uint32_t*)(g_att_h + rb + col) =
                pack2h(__float2half_rn(oacc[nt][0]), __float2half_rn(oacc[nt][1]));
        }
    }
    if (r_hi < NTOK) {
        size_t rb = obase + (size_t)r_hi * CCH;
#pragma unroll
        for (int nt = 0; nt < 4; nt++) {
            int col = nt * 8 + 2 * t;
            *(uint32_t*)(g_att_h + rb + col) =
                pack2h(__float2half_rn(oacc[nt][2]), __float2half_rn(oacc[nt][3]));
        }
    }
}

// ---------------------------------------------------------------------------
extern "C" void kernel_launch(void* const* d_in, const int* in_sizes, int n_in,
                              void* d_out, int out_size)
{
    const float* x      = (const float*)d_in[0];
    const float* qkv_w  = (const float*)d_in[1];
    const float* qkv_b  = (const float*)d_in[2];
    const float* proj_w = (const float*)d_in[3];
    const float* proj_b = (const float*)d_in[4];
    const float* rel    = (const float*)d_in[5];
    float* out = (float*)d_out;

    cudaFuncSetAttribute(gemm_mma_kernel<true>,
                         cudaFuncAttributeMaxDynamicSharedMemorySize, SMEM_DYN);
    cudaFuncSetAttribute(gemm_mma_kernel<false>,
                         cudaFuncAttributeMaxDynamicSharedMemorySize, SMEM_DYN);

    build_rowidx_kernel<<<(MROWS + 255) / 256, 256>>>();
    convert_w_kernel<<<(QKVC * CCH + 255) / 256, 256>>>(qkv_w, proj_w);
    build_bias_kernel<<<64, 256>>>(rel);
    convert_x_kernel<<<(int)(((size_t)MROWS * 128 + 255) / 256), 256>>>(x);

    // QKV: M=100352, N=1536 -> fp16 g_qkvh
    gemm_mma_kernel<true><<<dim3(QKVC / 128, MROWS / 128), 256, SMEM_DYN>>>(
        qkv_b, nullptr);

    attn_kernel<<<TOTWIN * NHEAD, 128>>>();

    // proj: M=100352, N=512 (A = g_att_h, scatter-C to out)
    gemm_mma_kernel<false><<<dim3(CCH / 128, MROWS / 128), 256, SMEM_DYN>>>(
        proj_b, out);
}